// round 5
// baseline (speedup 1.0000x reference)
#include <cuda_runtime.h>
#include <math.h>
#include <stdint.h>

#define BB 64
#define NNODES 128
#define HH 32
#define HEc 64
#define OEc 32
#define NT (BB*NNODES)
#define ALPHA 0.1f
#define BNEPS 1e-5f

static const double NE_D = 1048576.0;  // B*N*N edges
static const double NT_D = 8192.0;     // B*N nodes

typedef unsigned long long ull;

// ----------------- device scratch (no allocs allowed) -----------------
__device__ __align__(16) float g_x[NT*HH];
__device__ __align__(16) float g_Q1[NT*HEc];
__device__ __align__(16) float g_P2[NT*HEc];
__device__ __align__(16) float g_Sagg[NT*OEc];
__device__ __align__(16) float g_h1[NT*HH];
__device__ __align__(16) float g_h2[NT*HH];
__device__ double g_su[HEc],  g_ssu[HEc];
__device__ double g_sv[OEc],  g_ssv[OEc];
__device__ double g_sh0[HH],  g_ssh0[HH];
__device__ double g_sh1[HH],  g_ssh1[HH];
__device__ __align__(16) float g_Waf[HEc*OEc];
__device__ __align__(16) float g_baf[OEc];

__device__ __forceinline__ float lrelu(float z){ return fmaxf(z, ALPHA*z); }

// ---------------- packed f32x2 helpers (sm_100 base ISA) ---------------
__device__ __forceinline__ ull pack2(float lo, float hi){
    ull r; asm("mov.b64 %0, {%1, %2};" : "=l"(r) : "f"(lo), "f"(hi)); return r;
}
__device__ __forceinline__ void unpack2(ull a, float& lo, float& hi){
    asm("mov.b64 {%0, %1}, %2;" : "=f"(lo), "=f"(hi) : "l"(a));
}
__device__ __forceinline__ ull fma2(ull a, ull b, ull c){
    ull d; asm("fma.rn.f32x2 %0, %1, %2, %3;" : "=l"(d) : "l"(a), "l"(b), "l"(c)); return d;
}
__device__ __forceinline__ ull add2(ull a, ull b){
    ull d; asm("add.rn.f32x2 %0, %1, %2;" : "=l"(d) : "l"(a), "l"(b)); return d;
}
__device__ __forceinline__ ull mul2(ull a, ull b){
    ull d; asm("mul.rn.f32x2 %0, %1, %2;" : "=l"(d) : "l"(a), "l"(b)); return d;
}
// lrelu(z) = max(z, 0.1z) = 0.55*z + 0.45*|z|  (packed, ~1ulp)
#define C55_2 0x3F0CCCCD3F0CCCCDULL
#define C45_2 0x3EE666663EE66666ULL
#define ABSM2 0x7FFFFFFF7FFFFFFFULL
__device__ __forceinline__ ull lrelu2(ull z){
    return fma2(z, C55_2, mul2(z & ABSM2, C45_2));
}

// ----------------------------------------------------------------------
__global__ void k_zero(){
    int t = threadIdx.x;
    if (t < HEc){ g_su[t]=0.0; g_ssu[t]=0.0; }
    if (t < OEc){ g_sv[t]=0.0; g_ssv[t]=0.0; }
    if (t < HH){ g_sh0[t]=0.0; g_ssh0[t]=0.0; g_sh1[t]=0.0; g_ssh1[t]=0.0; }
}

__global__ void k_pad(const float* __restrict__ xin){
    int i = blockIdx.x*256 + threadIdx.x;
    if (i < NT*HH){
        int node = i >> 5, k = i & 31;
        g_x[i] = (k < 3) ? xin[node*3 + k] : 0.0f;
    }
}

// Q1 = x@Wah[0:32] + bah ; P2 = x@Wah[32:64]
__global__ void __launch_bounds__(256) k_pre(const float* __restrict__ Wah_i,
                                             const float* __restrict__ bah_i){
    __shared__ float xs[64*33];
    __shared__ float W1s[32*64];
    __shared__ float W2s[32*64];
    __shared__ float bs[64];
    int t = threadIdx.x;
    int n0 = blockIdx.x*64;
    for (int idx=t; idx<64*32; idx+=256){
        int n = idx>>5, k = idx&31;
        xs[n*33+k] = g_x[(n0+n)*32 + k];
    }
    for (int idx=t; idx<32*64; idx+=256){
        int k = idx>>6, c = idx&63;
        W1s[idx] = Wah_i[k*64 + c];
        W2s[idx] = Wah_i[(32+k)*64 + c];
    }
    if (t < 64) bs[t] = bah_i[t];
    __syncthreads();
    int c = t & 63, ng = t >> 6;
    for (int n=ng; n<64; n+=4){
        float q = bs[c], p = 0.0f;
        #pragma unroll
        for (int k=0;k<32;k++){
            float xv = xs[n*33+k];
            q = fmaf(xv, W1s[k*64+c], q);
            p = fmaf(xv, W2s[k*64+c], p);
        }
        g_Q1[(n0+n)*64 + c] = q;
        g_P2[(n0+n)*64 + c] = p;
    }
}

// ---------------- edge pass 1: stats of u = lrelu(z1), f32x2-packed ----
__global__ void __launch_bounds__(256) k_edge_stats(const float* __restrict__ Wah_i){
    extern __shared__ float sm[];
    float*  P2r = sm;                       // 8192
    float*  xr  = P2r + 8192;               // 4224
    float2* de  = (float2*)(xr + 4224);     // 2048 float2 (4096 f)
    float*  red = (float*)(de + 2048);      // 512

    int t  = threadIdx.x;
    int b  = blockIdx.y;
    int a0 = blockIdx.x*16;

    for (int idx=t; idx<2048; idx+=256)
        ((float4*)P2r)[idx] = ((const float4*)(g_P2 + b*8192))[idx];
    for (int idx=t; idx<4096; idx+=256){
        int r = idx>>5, kk = idx&31;
        xr[r*33+kk] = g_x[b*4096 + idx];
    }
    __syncthreads();

    #pragma unroll
    for (int j=0;j<8;j++){
        int e  = t + 256*j;
        int as = e >> 7, p = e & 127;
        const float* xra = xr + (a0+as)*33;
        const float* xrp = xr + p*33;
        float s = 0.0f;
        #pragma unroll
        for (int kk=0;kk<31;kk++){
            float df = xrp[kk] - xra[kk] + 1e-12f;
            s = fmaf(df, df, s);
        }
        de[e] = make_float2(sqrtf(s), 1.0f - (xrp[31]-xra[31]));
    }
    __syncthreads();

    int kp = t & 31, g = t >> 5;       // k-pair, p-group
    int k0 = 2*kp;
    float2 wdf = *(const float2*)(Wah_i + 64*64 + k0);
    float2 wif = *(const float2*)(Wah_i + 65*64 + k0);
    ull wd2 = pack2(wdf.x, wdf.y);
    ull wi2 = pack2(wif.x, wif.y);
    ull q2[16];
    #pragma unroll
    for (int as=0; as<16; as++){
        float2 qf = *(const float2*)(g_Q1 + (size_t)(b*128+a0+as)*64 + k0);
        q2[as] = pack2(qf.x, qf.y);
    }

    ull su2 = 0, ssu2 = 0;
    for (int m=0;m<16;m++){
        int p = g + 8*m;
        float2 pvf = *(const float2*)(P2r + p*64 + k0);
        ull pv2 = pack2(pvf.x, pvf.y);
        #pragma unroll
        for (int as=0; as<16; as++){
            float2 e2 = de[as*128+p];
            ull dx2 = pack2(e2.x, e2.x);
            ull ii2 = pack2(e2.y, e2.y);
            ull z2 = fma2(dx2, wd2, add2(q2[as], pv2));
            z2 = fma2(ii2, wi2, z2);
            ull u2 = lrelu2(z2);
            su2 = add2(su2, u2);
            ssu2 = fma2(u2, u2, ssu2);
        }
    }
    {
        float sx, sy; unpack2(su2, sx, sy);
        red[g*64 + k0] = sx; red[g*64 + k0 + 1] = sy;
    }
    __syncthreads();
    if (t < 64){
        float S = 0.0f;
        #pragma unroll
        for (int j=0;j<8;j++) S += red[j*64 + t];
        atomicAdd(&g_su[t], (double)S);
    }
    __syncthreads();
    {
        float sx, sy; unpack2(ssu2, sx, sy);
        red[g*64 + k0] = sx; red[g*64 + k0 + 1] = sy;
    }
    __syncthreads();
    if (t < 64){
        float S = 0.0f;
        #pragma unroll
        for (int j=0;j<8;j++) S += red[j*64 + t];
        atomicAdd(&g_ssu[t], (double)S);
    }
}

// ---------------- fold BN1 into GEMM2 ----------------------------------
__global__ void k_fold1(const float* __restrict__ Wa_i, const float* __restrict__ ba_i,
                        const float* __restrict__ geh,  const float* __restrict__ beh){
    __shared__ float s1[64], t1[64];
    int t = threadIdx.x;
    if (t < 64){
        double m = g_su[t]/NE_D;
        double v = g_ssu[t]/NE_D - m*m;
        float s = geh[t] * rsqrtf((float)v + BNEPS);
        s1[t] = s; t1[t] = beh[t] - (float)m*s;
    }
    __syncthreads();
    for (int idx=t; idx<64*32; idx+=256){
        int k = idx>>5;
        g_Waf[idx] = s1[k]*Wa_i[idx];
    }
    if (t < 32){
        float acc = ba_i[t];
        #pragma unroll
        for (int k=0;k<64;k++) acc = fmaf(t1[k], Wa_i[k*32+t], acc);
        g_baf[t] = acc;
    }
}

// ---------------- edge pass 2: main, f32x2 edge-pair-packed GEMM -------
// smem (floats from aligned base): P2r 8192 | us_i 8192 (alias xr) |
//   de 4096 | wsh2 4096 (ull[2048]) | red2 512 | bafs 32
#define OFF_P2R  0
#define OFF_USI  8192
#define OFF_DE   16384
#define OFF_WSH  20480
#define OFF_RED2 24576
#define OFF_BAF  25088
#define SMEM_MAIN_F (25120)
#define SMEM_MAIN_BYTES (SMEM_MAIN_F*4 + 1024)

__global__ void __launch_bounds__(256) k_edge_main(const float* __restrict__ Wah_i){
    extern __shared__ char smraw[];
    float* A0 = (float*)(((uintptr_t)smraw + 1023) & ~(uintptr_t)1023);

    float*  P2r  = A0 + OFF_P2R;
    float*  us_i = A0 + OFF_USI;
    float*  xr   = us_i;                    // transient alias (4224 f)
    float2* de   = (float2*)(A0 + OFF_DE);
    ull*    wsh2 = (ull*)(A0 + OFF_WSH);    // 2048 ull: [kk][c] packed (w,w)
    float*  red2 = A0 + OFF_RED2;           // 512
    float*  bafs = A0 + OFF_BAF;            // 32

    int t  = threadIdx.x;
    int b  = blockIdx.y;
    int a0 = blockIdx.x*16;

    // --- loads ---
    for (int idx=t; idx<2048; idx+=256)
        ((float4*)P2r)[idx] = ((const float4*)(g_P2 + b*8192))[idx];
    for (int idx=t; idx<4096; idx+=256){
        int r = idx>>5, kk = idx&31;
        xr[r*33+kk] = g_x[b*4096 + idx];
    }
    for (int idx=t; idx<2048; idx+=256){
        float w = g_Waf[idx];
        wsh2[idx] = pack2(w, w);
    }
    if (t < 32) bafs[t] = g_baf[t];
    __syncthreads();

    // --- distances (reads xr; after sync, us_i overwrites that region) ---
    #pragma unroll
    for (int j=0;j<8;j++){
        int e  = t + 256*j;
        int as = e >> 7, p = e & 127;
        const float* xra = xr + (a0+as)*33;
        const float* xrp = xr + p*33;
        float s = 0.0f;
        #pragma unroll
        for (int kk=0;kk<31;kk++){
            float df = xrp[kk] - xra[kk] + 1e-12f;
            s = fmaf(df, df, s);
        }
        de[e] = make_float2(sqrtf(s), 1.0f - (xrp[31]-xra[31]));
    }
    __syncthreads();

    // phase A mapping: k channel + 2-edge packing
    int kA  = t & 63;
    int pg4 = t >> 6;                     // 0..3
    float wdA = Wah_i[64*64 + kA];
    float wiA = Wah_i[65*64 + kA];
    ull wd2A = pack2(wdA, wdA);
    ull wi2A = pack2(wiA, wiA);
    const float4* de4 = (const float4*)de;

    // phase B mapping
    int c = t & 31, gy = t >> 5;
    float bafc = bafs[c];
    float ssv = 0.0f;
    float vtot = 0.0f;                    // t<32 only

    for (int as=0; as<16; as++){
        // ---- phase A: u for all 128 receivers, interleaved pair layout ----
        {
            float qA = g_Q1[(size_t)(b*128 + a0 + as)*64 + kA];
            #pragma unroll
            for (int j=0;j<16;j++){
                int e  = pg4 + 4*j;       // pair 0..63
                int p0 = 2*e;
                float4 dd = de4[as*64 + e];          // (d0,i0,d1,i1)
                float pv0 = P2r[p0*64 + kA];
                float pv1 = P2r[p0*64 + 64 + kA];
                ull qpv = pack2(qA + pv0, qA + pv1);
                ull z2 = fma2(pack2(dd.x, dd.z), wd2A, qpv);
                z2 = fma2(pack2(dd.y, dd.w), wi2A, z2);
                *(ull*)(us_i + e*128 + 2*kA) = lrelu2(z2);
            }
        }
        __syncthreads();

        // ---- phase B: packed 64x32 GEMM over 8 edge-pairs per thread ----
        {
            ull acc[8];
            #pragma unroll
            for (int jj=0;jj<8;jj++) acc[jj] = 0;
            #pragma unroll
            for (int half=0; half<2; half++){
                ull w2h[32];
                #pragma unroll
                for (int kk=0;kk<32;kk++)
                    w2h[kk] = wsh2[(half*32+kk)*32 + c];
                #pragma unroll
                for (int jj=0;jj<8;jj++){
                    int pr = gy*8 + jj;
                    const ulonglong2* uu2 =
                        (const ulonglong2*)(us_i + pr*128 + half*64);
                    ull ae = 0, ao = 0;
                    #pragma unroll
                    for (int kk=0;kk<16;kk++){
                        ulonglong2 uu = uu2[kk];
                        ae = fma2(uu.x, w2h[2*kk],   ae);
                        ao = fma2(uu.y, w2h[2*kk+1], ao);
                    }
                    acc[jj] = add2(acc[jj], add2(ae, ao));
                }
            }
            float vsum = 0.0f;
            #pragma unroll
            for (int jj=0;jj<8;jj++){
                float y0, y1; unpack2(acc[jj], y0, y1);
                y0 += bafc; y1 += bafc;
                float v0 = fmaxf(y0, ALPHA*y0);
                float v1 = fmaxf(y1, ALPHA*y1);
                vsum += v0 + v1;
                ssv = fmaf(v0, v0, ssv);
                ssv = fmaf(v1, v1, ssv);
            }
            red2[gy*32 + c] = vsum;
        }
        __syncthreads();
        if (t < 32){
            float S = 0.0f;
            #pragma unroll
            for (int j=0;j<8;j++) S += red2[j*32 + t];
            g_Sagg[(b*128 + a0 + as)*32 + t] = S;
            vtot += S;
        }
        __syncthreads();
    }

    // block-reduce ssv
    red2[gy*32 + c] = ssv;
    __syncthreads();
    if (t < 32){
        float S = 0.0f;
        #pragma unroll
        for (int j=0;j<8;j++) S += red2[j*32 + t];
        atomicAdd(&g_ssv[t], (double)S);
        atomicAdd(&g_sv[t],  (double)vtot);
    }
}

// ---------------- node layer 0 -----------------------------------------
__global__ void __launch_bounds__(256) k_node0(const float* __restrict__ Wn0_i,
                                               const float* __restrict__ bn0_i,
                                               const float* __restrict__ ge_i,
                                               const float* __restrict__ be_i){
    __shared__ float W[2048];
    __shared__ float s2[32], t2[32], bsh[32], ssum[32], sssum[32];
    int t = threadIdx.x;
    if (t < 32){
        double m = g_sv[t]/NE_D;
        double v = g_ssv[t]/NE_D - m*m;
        float s = ge_i[t] * rsqrtf((float)v + BNEPS);
        s2[t] = s; t2[t] = be_i[t] - (float)m*s;
        bsh[t] = bn0_i[t]; ssum[t] = 0.0f; sssum[t] = 0.0f;
    }
    for (int idx=t; idx<2048; idx+=256) W[idx] = Wn0_i[idx];
    __syncthreads();

    int row = blockIdx.x*256 + t;
    float in[64];
    #pragma unroll
    for (int cc=0;cc<32;cc++){
        in[cc]    = fmaf(s2[cc], g_Sagg[row*32+cc], 128.0f*t2[cc]);
        in[32+cc] = g_x[row*32+cc];
    }
    float z[32];
    #pragma unroll
    for (int cc=0;cc<32;cc++) z[cc] = bsh[cc];
    #pragma unroll
    for (int kk=0;kk<64;kk++){
        float xv = in[kk];
        #pragma unroll
        for (int cc=0;cc<32;cc++) z[cc] = fmaf(xv, W[kk*32+cc], z[cc]);
    }
    int lane = t & 31;
    #pragma unroll
    for (int cc=0;cc<32;cc++){
        float h = lrelu(z[cc]);
        g_h1[row*32+cc] = h;
        float v1 = h, v2 = h*h;
        #pragma unroll
        for (int off=16; off>0; off>>=1){
            v1 += __shfl_xor_sync(0xFFFFFFFFu, v1, off);
            v2 += __shfl_xor_sync(0xFFFFFFFFu, v2, off);
        }
        if (lane == 0){ atomicAdd(&ssum[cc], v1); atomicAdd(&sssum[cc], v2); }
    }
    __syncthreads();
    if (t < 32){
        atomicAdd(&g_sh0[t], (double)ssum[t]);
        atomicAdd(&g_ssh0[t], (double)sssum[t]);
    }
}

// ---------------- node layer 1 -----------------------------------------
__global__ void __launch_bounds__(256) k_node1(const float* __restrict__ Wn_i,
                                               const float* __restrict__ bnn_i,
                                               const float* __restrict__ gn0,
                                               const float* __restrict__ bn0v){
    __shared__ float W[1024];
    __shared__ float s0[32], t0[32], bsh[32], ssum[32], sssum[32];
    int t = threadIdx.x;
    if (t < 32){
        double m = g_sh0[t]/NT_D;
        double v = g_ssh0[t]/NT_D - m*m;
        float s = gn0[t] * rsqrtf((float)v + BNEPS);
        s0[t] = s; t0[t] = bn0v[t] - (float)m*s;
        bsh[t] = bnn_i[t]; ssum[t] = 0.0f; sssum[t] = 0.0f;
    }
    for (int idx=t; idx<1024; idx+=256) W[idx] = Wn_i[idx];
    __syncthreads();

    int row = blockIdx.x*256 + t;
    float hn[32];
    #pragma unroll
    for (int kk=0;kk<32;kk++) hn[kk] = fmaf(s0[kk], g_h1[row*32+kk], t0[kk]);
    float z[32];
    #pragma unroll
    for (int cc=0;cc<32;cc++) z[cc] = bsh[cc];
    #pragma unroll
    for (int kk=0;kk<32;kk++){
        float xv = hn[kk];
        #pragma unroll
        for (int cc=0;cc<32;cc++) z[cc] = fmaf(xv, W[kk*32+cc], z[cc]);
    }
    int lane = t & 31;
    #pragma unroll
    for (int cc=0;cc<32;cc++){
        float h = lrelu(z[cc]);
        g_h2[row*32+cc] = h;
        float v1 = h, v2 = h*h;
        #pragma unroll
        for (int off=16; off>0; off>>=1){
            v1 += __shfl_xor_sync(0xFFFFFFFFu, v1, off);
            v2 += __shfl_xor_sync(0xFFFFFFFFu, v2, off);
        }
        if (lane == 0){ atomicAdd(&ssum[cc], v1); atomicAdd(&sssum[cc], v2); }
    }
    __syncthreads();
    if (t < 32){
        atomicAdd(&g_sh1[t], (double)ssum[t]);
        atomicAdd(&g_ssh1[t], (double)sssum[t]);
    }
}

// ---------------- node final: update linear + tanh ---------------------
__global__ void __launch_bounds__(256) k_node2(const float* __restrict__ Wu_i,
                                               const float* __restrict__ bu_i,
                                               const float* __restrict__ gn1,
                                               const float* __restrict__ bn1v,
                                               float* __restrict__ out,
                                               int is_last){
    __shared__ float W[1024];
    __shared__ float s0[32], t0[32], bsh[32];
    int t = threadIdx.x;
    if (t < 32){
        double m = g_sh1[t]/NT_D;
        double v = g_ssh1[t]/NT_D - m*m;
        float s = gn1[t] * rsqrtf((float)v + BNEPS);
        s0[t] = s; t0[t] = bn1v[t] - (float)m*s;
        bsh[t] = bu_i[t];
    }
    for (int idx=t; idx<1024; idx+=256) W[idx] = Wu_i[idx];
    __syncthreads();

    int row = blockIdx.x*256 + t;
    float hn[32];
    #pragma unroll
    for (int kk=0;kk<32;kk++) hn[kk] = fmaf(s0[kk], g_h2[row*32+kk], t0[kk]);
    float z[32];
    #pragma unroll
    for (int cc=0;cc<32;cc++) z[cc] = bsh[cc];
    #pragma unroll
    for (int kk=0;kk<32;kk++){
        float xv = hn[kk];
        #pragma unroll
        for (int cc=0;cc<32;cc++) z[cc] = fmaf(xv, W[kk*32+cc], z[cc]);
    }
    #pragma unroll
    for (int cc=0;cc<32;cc++){
        float o = tanhf(z[cc]);
        g_x[row*32+cc] = o;
        if (is_last) out[row*32+cc] = o;
    }
}

// ----------------------------------------------------------------------
extern "C" void kernel_launch(void* const* d_in, const int* in_sizes, int n_in,
                              void* d_out, int out_size){
    const float* x    = (const float*)d_in[0];
    const float* Wah  = (const float*)d_in[1];
    const float* bah  = (const float*)d_in[2];
    const float* Wa   = (const float*)d_in[3];
    const float* ba   = (const float*)d_in[4];
    const float* geh  = (const float*)d_in[5];
    const float* beh  = (const float*)d_in[6];
    const float* ge   = (const float*)d_in[7];
    const float* be   = (const float*)d_in[8];
    const float* Wn0  = (const float*)d_in[9];
    const float* bn0  = (const float*)d_in[10];
    const float* Wn   = (const float*)d_in[11];
    const float* bnn  = (const float*)d_in[12];
    const float* gn   = (const float*)d_in[13];
    const float* bnv  = (const float*)d_in[14];
    const float* Wu   = (const float*)d_in[15];
    const float* bu   = (const float*)d_in[16];
    float* out = (float*)d_out;

    const size_t SMEM_STATS = (8192 + 4224 + 4096 + 512)*sizeof(float);
    cudaFuncSetAttribute(k_edge_stats, cudaFuncAttributeMaxDynamicSharedMemorySize, (int)SMEM_STATS);
    cudaFuncSetAttribute(k_edge_main,  cudaFuncAttributeMaxDynamicSharedMemorySize, SMEM_MAIN_BYTES);

    k_pad<<<NT*HH/256, 256>>>(x);

    for (int i=0; i<4; i++){
        k_zero<<<1,128>>>();
        k_pre<<<128,256>>>(Wah + i*66*64, bah + i*64);
        k_edge_stats<<<dim3(8,64),256,SMEM_STATS>>>(Wah + i*66*64);
        k_fold1<<<1,256>>>(Wa + i*64*32, ba + i*32, geh + i*64, beh + i*64);
        k_edge_main<<<dim3(8,64),256,SMEM_MAIN_BYTES>>>(Wah + i*66*64);
        k_node0<<<32,256>>>(Wn0 + i*64*32, bn0 + i*32, ge + i*32, be + i*32);
        k_node1<<<32,256>>>(Wn + i*32*32, bnn + i*32, gn + (i*2+0)*32, bnv + (i*2+0)*32);
        k_node2<<<32,256>>>(Wu + i*32*32, bu + i*32, gn + (i*2+1)*32, bnv + (i*2+1)*32,
                            out, (i==3) ? 1 : 0);
    }
}

// round 6
// speedup vs baseline: 1.8277x; 1.8277x over previous
#include <cuda_runtime.h>
#include <cuda_bf16.h>
#include <math.h>
#include <stdint.h>

#define BB 64
#define NNODES 128
#define HH 32
#define HEc 64
#define OEc 32
#define NT (BB*NNODES)
#define ALPHA 0.1f
#define BNEPS 1e-5f

static const double NE_D = 1048576.0;  // B*N*N edges
static const double NT_D = 8192.0;     // B*N nodes

// ----------------- device scratch (no allocs allowed) -----------------
__device__ __align__(16) float g_x[NT*HH];
__device__ __align__(16) float g_Q1[NT*HEc];
__device__ __align__(16) float g_P2[NT*HEc];
__device__ __align__(16) float g_Sagg[NT*OEc];
__device__ __align__(16) float g_h1[NT*HH];
__device__ __align__(16) float g_h2[NT*HH];
__device__ double g_su[HEc],  g_ssu[HEc];
__device__ double g_sv[OEc],  g_ssv[OEc];
__device__ double g_sh0[HH],  g_ssh0[HH];
__device__ double g_sh1[HH],  g_ssh1[HH];
__device__ __align__(16) float g_baf[OEc];
// W^T folded (BN1) and split: [c][k], 32x64 bf16 each
__device__ __align__(16) __nv_bfloat16 g_Wthi[OEc*HEc];
__device__ __align__(16) __nv_bfloat16 g_Wtlo[OEc*HEc];

__device__ __forceinline__ float lrelu(float z){ return fmaxf(z, ALPHA*z); }

// ---------------- warp-MMA helpers (base ISA: sm_80+) -------------------
__device__ __forceinline__ uint32_t s2u(const void* p){
    return (uint32_t)__cvta_generic_to_shared(p);
}
__device__ __forceinline__ void ldmx4(uint32_t* r, uint32_t a){
    asm volatile("ldmatrix.sync.aligned.m8n8.x4.shared.b16 {%0,%1,%2,%3}, [%4];"
        : "=r"(r[0]),"=r"(r[1]),"=r"(r[2]),"=r"(r[3]) : "r"(a));
}
__device__ __forceinline__ void ldmx2(uint32_t* r, uint32_t a){
    asm volatile("ldmatrix.sync.aligned.m8n8.x2.shared.b16 {%0,%1}, [%2];"
        : "=r"(r[0]),"=r"(r[1]) : "r"(a));
}
__device__ __forceinline__ void mma16816(float* c, const uint32_t* a, const uint32_t* b){
    asm volatile("mma.sync.aligned.m16n8k16.row.col.f32.bf16.bf16.f32 "
        "{%0,%1,%2,%3}, {%4,%5,%6,%7}, {%8,%9}, {%0,%1,%2,%3};"
        : "+f"(c[0]),"+f"(c[1]),"+f"(c[2]),"+f"(c[3])
        : "r"(a[0]),"r"(a[1]),"r"(a[2]),"r"(a[3]), "r"(b[0]),"r"(b[1]));
}

// ----------------------------------------------------------------------
__global__ void k_zero(){
    int t = threadIdx.x;
    if (t < HEc){ g_su[t]=0.0; g_ssu[t]=0.0; }
    if (t < OEc){ g_sv[t]=0.0; g_ssv[t]=0.0; }
    if (t < HH){ g_sh0[t]=0.0; g_ssh0[t]=0.0; g_sh1[t]=0.0; g_ssh1[t]=0.0; }
}

__global__ void k_pad(const float* __restrict__ xin){
    int i = blockIdx.x*256 + threadIdx.x;
    if (i < NT*HH){
        int node = i >> 5, k = i & 31;
        g_x[i] = (k < 3) ? xin[node*3 + k] : 0.0f;
    }
}

// Q1 = x@Wah[0:32] + bah ; P2 = x@Wah[32:64]
__global__ void __launch_bounds__(256) k_pre(const float* __restrict__ Wah_i,
                                             const float* __restrict__ bah_i){
    __shared__ float xs[64*33];
    __shared__ float W1s[32*64];
    __shared__ float W2s[32*64];
    __shared__ float bs[64];
    int t = threadIdx.x;
    int n0 = blockIdx.x*64;
    for (int idx=t; idx<64*32; idx+=256){
        int n = idx>>5, k = idx&31;
        xs[n*33+k] = g_x[(n0+n)*32 + k];
    }
    for (int idx=t; idx<32*64; idx+=256){
        int k = idx>>6, c = idx&63;
        W1s[idx] = Wah_i[k*64 + c];
        W2s[idx] = Wah_i[(32+k)*64 + c];
    }
    if (t < 64) bs[t] = bah_i[t];
    __syncthreads();
    int c = t & 63, ng = t >> 6;
    for (int n=ng; n<64; n+=4){
        float q = bs[c], p = 0.0f;
        #pragma unroll
        for (int k=0;k<32;k++){
            float xv = xs[n*33+k];
            q = fmaf(xv, W1s[k*64+c], q);
            p = fmaf(xv, W2s[k*64+c], p);
        }
        g_Q1[(n0+n)*64 + c] = q;
        g_P2[(n0+n)*64 + c] = p;
    }
}

// ---------------- edge pass 1: stats of u = lrelu(z1), 8 senders/block -
__global__ void __launch_bounds__(256) k_edge_stats(const float* __restrict__ Wah_i){
    extern __shared__ float sm[];
    float*  P2r = sm;                       // 8192
    float*  xr  = P2r + 8192;               // 4224
    float2* de  = (float2*)(xr + 4224);     // up to 2048 float2 (1024 used)
    float*  red = (float*)(de + 2048);      // 256

    int t  = threadIdx.x;
    int b  = blockIdx.y;
    int a0 = blockIdx.x*8;

    for (int idx=t; idx<2048; idx+=256)
        ((float4*)P2r)[idx] = ((const float4*)(g_P2 + b*8192))[idx];
    for (int idx=t; idx<4096; idx+=256){
        int r = idx>>5, kk = idx&31;
        xr[r*33+kk] = g_x[b*4096 + idx];
    }
    __syncthreads();

    #pragma unroll
    for (int j=0;j<4;j++){
        int e  = t + 256*j;
        int as = e >> 7, p = e & 127;
        const float* xra = xr + (a0+as)*33;
        const float* xrp = xr + p*33;
        float s = 0.0f;
        #pragma unroll
        for (int kk=0;kk<31;kk++){
            float df = xrp[kk] - xra[kk] + 1e-12f;
            s = fmaf(df, df, s);
        }
        de[e] = make_float2(sqrtf(s), 1.0f - (xrp[31]-xra[31]));
    }
    __syncthreads();

    int k = t & 63, g = t >> 6;
    float wdk = Wah_i[64*64 + k];
    float wik = Wah_i[65*64 + k];
    float q[8];
    #pragma unroll
    for (int as=0; as<8; as++) q[as] = g_Q1[(b*128+a0+as)*64 + k];

    float su = 0.0f, ssu = 0.0f;
    for (int p=g; p<128; p+=4){
        float pv = P2r[p*64+k];
        #pragma unroll
        for (int as=0; as<8; as++){
            float2 e2 = de[as*128+p];
            float z = fmaf(e2.x, wdk, q[as] + pv);
            z = fmaf(e2.y, wik, z);
            float u = fmaxf(z, ALPHA*z);
            su += u; ssu = fmaf(u,u,ssu);
        }
    }
    red[g*64+k] = su;
    __syncthreads();
    if (g == 0)
        atomicAdd(&g_su[k], (double)(red[k]+red[64+k]+red[128+k]+red[192+k]));
    __syncthreads();
    red[g*64+k] = ssu;
    __syncthreads();
    if (g == 0)
        atomicAdd(&g_ssu[k], (double)(red[k]+red[64+k]+red[128+k]+red[192+k]));
}

// ---------------- fold BN1 into W^T (bf16 hi/lo split) ------------------
__global__ void k_fold1(const float* __restrict__ Wa_i, const float* __restrict__ ba_i,
                        const float* __restrict__ geh,  const float* __restrict__ beh){
    __shared__ float s1[64], t1[64];
    int t = threadIdx.x;
    if (t < 64){
        double m = g_su[t]/NE_D;
        double v = g_ssu[t]/NE_D - m*m;
        float s = geh[t] * rsqrtf((float)v + BNEPS);
        s1[t] = s; t1[t] = beh[t] - (float)m*s;
    }
    __syncthreads();
    for (int idx=t; idx<2048; idx+=256){
        int c = idx>>6, k = idx&63;
        float w = s1[k]*Wa_i[k*32+c];
        __nv_bfloat16 hi = __float2bfloat16(w);
        g_Wthi[idx] = hi;
        g_Wtlo[idx] = __float2bfloat16(w - __bfloat162float(hi));
    }
    if (t < 32){
        float acc = ba_i[t];
        #pragma unroll
        for (int k=0;k<64;k++) acc = fmaf(t1[k], Wa_i[k*32+t], acc);
        g_baf[t] = acc;
    }
}

// ---------------- edge pass 2: HMMA main kernel -------------------------
// byte offsets from 1024-aligned base
#define OFF_P2R   0        // 32768
#define OFF_DE    32768    // 16384
#define OFF_Q1A   49152    // 4096
#define OFF_UHI   53248    // 18432 (rows 144B)  [xr transient alias]
#define OFF_ULO   71680    // 18432
#define OFF_WTHI  90112    // 4608 (32 rows x 144B)
#define OFF_WTLO  94720    // 4608
#define OFF_RED   99328    // 2048 (two 8x32 float)
#define OFF_BAF   101376   // 128
#define SMEM_MAIN_BYTES (1024 + 101504)
#define ROWB 144

__global__ void __launch_bounds__(256, 1) k_edge_main(const float* __restrict__ Wah_i){
    extern __shared__ char smraw[];
    char* A0 = (char*)(((uintptr_t)smraw + 1023) & ~(uintptr_t)1023);

    float*  P2r  = (float*)(A0 + OFF_P2R);
    float2* de   = (float2*)(A0 + OFF_DE);
    float*  Q1a  = (float*)(A0 + OFF_Q1A);
    char*   uhi  = A0 + OFF_UHI;
    char*   ulo  = A0 + OFF_ULO;
    char*   wthi = A0 + OFF_WTHI;
    char*   wtlo = A0 + OFF_WTLO;
    float*  xr   = (float*)uhi;            // transient (4224 f <= 36864B)
    float*  red  = (float*)(A0 + OFF_RED); // [8][32]
    float*  sqr  = red + 256;              // [8][32]
    float*  bafs = (float*)(A0 + OFF_BAF);

    int t    = threadIdx.x;
    int w    = t >> 5, lane = t & 31;
    int b    = blockIdx.y;
    int a0   = blockIdx.x*16;

    // --- prologue loads ---
    for (int idx=t; idx<2048; idx+=256)
        ((float4*)P2r)[idx] = ((const float4*)(g_P2 + b*8192))[idx];
    for (int idx=t; idx<4096; idx+=256){
        int r = idx>>5, kk = idx&31;
        xr[r*33+kk] = g_x[b*4096 + idx];
    }
    for (int idx=t; idx<1024; idx+=256)
        Q1a[idx] = g_Q1[(size_t)(b*128+a0)*64 + idx];
    for (int idx=t; idx<2048; idx+=256){
        int c = idx>>6, k = idx&63;
        *(__nv_bfloat16*)(wthi + c*ROWB + k*2) = g_Wthi[idx];
        *(__nv_bfloat16*)(wtlo + c*ROWB + k*2) = g_Wtlo[idx];
    }
    if (t < 32) bafs[t] = g_baf[t];
    __syncthreads();

    // --- distances (reads xr) ---
    #pragma unroll
    for (int j=0;j<8;j++){
        int e  = t + 256*j;
        int as = e >> 7, p = e & 127;
        const float* xra = xr + (a0+as)*33;
        const float* xrp = xr + p*33;
        float s = 0.0f;
        #pragma unroll
        for (int kk=0;kk<31;kk++){
            float df = xrp[kk] - xra[kk] + 1e-12f;
            s = fmaf(df, df, s);
        }
        de[e] = make_float2(sqrtf(s), 1.0f - (xrp[31]-xra[31]));
    }
    __syncthreads();   // xr dead; uhi/ulo region free to write

    // --- persistent B fragments (W^T), per warp ---
    uint32_t bh[4][4][2], bl[4][4][2];
    {
        int li = lane & 15;
        uint32_t rsel = (uint32_t)((li & 7)*ROWB);
        uint32_t ksel = (uint32_t)((li >> 3)*16);
        #pragma unroll
        for (int kt=0; kt<4; kt++){
            #pragma unroll
            for (int nt=0; nt<4; nt++){
                uint32_t off = (uint32_t)(nt*8*ROWB) + rsel + (uint32_t)(kt*32) + ksel;
                ldmx2(bh[kt][nt], s2u(wthi) + off);
                ldmx2(bl[kt][nt], s2u(wtlo) + off);
            }
        }
    }
    // bias regs per lane
    int tc = lane & 3;
    float bias0[4], bias1[4];
    #pragma unroll
    for (int nt=0; nt<4; nt++){
        bias0[nt] = bafs[8*nt + 2*tc];
        bias1[nt] = bafs[8*nt + 2*tc + 1];
    }

    // phase-A per-thread constants
    int kp = lane;                         // k-pair 0..31
    float wd0 = Wah_i[64*64 + 2*kp], wd1 = Wah_i[64*64 + 2*kp + 1];
    float wi0 = Wah_i[65*64 + 2*kp], wi1 = Wah_i[65*64 + 2*kp + 1];

    // A ldmatrix per-lane base offset within tile
    uint32_t aoff = (uint32_t)((w*16 + (lane & 15))*ROWB) + ((lane & 16) ? 16u : 0u);
    uint32_t uhiB = s2u(uhi), uloB = s2u(ulo);

    float vtot = 0.0f, ssvtot = 0.0f;      // t<32 only

    for (int as=0; as<16; as++){
        // ---- phase A: u -> bf16 hi/lo tiles ----
        {
            float2 q = *(const float2*)(Q1a + as*64 + 2*kp);
            #pragma unroll
            for (int j=0;j<16;j++){
                int p = w + 8*j;
                float2 pv = *(const float2*)(P2r + p*64 + 2*kp);
                float2 dd = de[as*128 + p];
                float z0 = fmaf(dd.x, wd0, q.x + pv.x); z0 = fmaf(dd.y, wi0, z0);
                float z1 = fmaf(dd.x, wd1, q.y + pv.y); z1 = fmaf(dd.y, wi1, z1);
                float u0 = fmaxf(z0, ALPHA*z0);
                float u1 = fmaxf(z1, ALPHA*z1);
                __nv_bfloat162 h2 = __floats2bfloat162_rn(u0, u1);
                float2 hf = __bfloat1622float2(h2);
                __nv_bfloat162 l2 = __floats2bfloat162_rn(u0 - hf.x, u1 - hf.y);
                *(__nv_bfloat162*)(uhi + p*ROWB + kp*4) = h2;
                *(__nv_bfloat162*)(ulo + p*ROWB + kp*4) = l2;
            }
        }
        __syncthreads();

        // ---- phase B: 3-pass bf16 HMMA, accumulate fp32 ----
        float C[4][4];
        #pragma unroll
        for (int nt=0;nt<4;nt++){
            C[nt][0]=0.f; C[nt][1]=0.f; C[nt][2]=0.f; C[nt][3]=0.f;
        }
        #pragma unroll
        for (int kt=0; kt<4; kt++){
            uint32_t ah[4], al[4];
            ldmx4(ah, uhiB + aoff + kt*32);
            ldmx4(al, uloB + aoff + kt*32);
            #pragma unroll
            for (int nt=0; nt<4; nt++){
                mma16816(C[nt], ah, bh[kt][nt]);
                mma16816(C[nt], ah, bl[kt][nt]);
                mma16816(C[nt], al, bh[kt][nt]);
            }
        }

        // ---- epilogue: bias + lrelu, row-sum + sq-sum per channel ----
        #pragma unroll
        for (int nt=0; nt<4; nt++){
            float y00 = C[nt][0] + bias0[nt];
            float y01 = C[nt][1] + bias1[nt];
            float y10 = C[nt][2] + bias0[nt];
            float y11 = C[nt][3] + bias1[nt];
            float v00 = fmaxf(y00, ALPHA*y00);
            float v01 = fmaxf(y01, ALPHA*y01);
            float v10 = fmaxf(y10, ALPHA*y10);
            float v11 = fmaxf(y11, ALPHA*y11);
            float cs0 = v00 + v10, cs1 = v01 + v11;
            float sq0 = fmaf(v00,v00, v10*v10);
            float sq1 = fmaf(v01,v01, v11*v11);
            #pragma unroll
            for (int off=4; off<32; off<<=1){
                cs0 += __shfl_xor_sync(0xFFFFFFFFu, cs0, off);
                cs1 += __shfl_xor_sync(0xFFFFFFFFu, cs1, off);
                sq0 += __shfl_xor_sync(0xFFFFFFFFu, sq0, off);
                sq1 += __shfl_xor_sync(0xFFFFFFFFu, sq1, off);
            }
            if (lane < 4){
                red[w*32 + 8*nt + 2*tc]     = cs0;
                red[w*32 + 8*nt + 2*tc + 1] = cs1;
                sqr[w*32 + 8*nt + 2*tc]     = sq0;
                sqr[w*32 + 8*nt + 2*tc + 1] = sq1;
            }
        }
        __syncthreads();
        if (t < 32){
            float S = 0.0f, SS = 0.0f;
            #pragma unroll
            for (int j=0;j<8;j++){ S += red[j*32 + t]; SS += sqr[j*32 + t]; }
            g_Sagg[(size_t)(b*128 + a0 + as)*32 + t] = S;
            vtot += S; ssvtot += SS;
        }
    }

    if (t < 32){
        atomicAdd(&g_sv[t],  (double)vtot);
        atomicAdd(&g_ssv[t], (double)ssvtot);
    }
}

// ---------------- node layer 0 -----------------------------------------
__global__ void __launch_bounds__(256) k_node0(const float* __restrict__ Wn0_i,
                                               const float* __restrict__ bn0_i,
                                               const float* __restrict__ ge_i,
                                               const float* __restrict__ be_i){
    __shared__ float W[2048];
    __shared__ float s2[32], t2[32], bsh[32], ssum[32], sssum[32];
    int t = threadIdx.x;
    if (t < 32){
        double m = g_sv[t]/NE_D;
        double v = g_ssv[t]/NE_D - m*m;
        float s = ge_i[t] * rsqrtf((float)v + BNEPS);
        s2[t] = s; t2[t] = be_i[t] - (float)m*s;
        bsh[t] = bn0_i[t]; ssum[t] = 0.0f; sssum[t] = 0.0f;
    }
    for (int idx=t; idx<2048; idx+=256) W[idx] = Wn0_i[idx];
    __syncthreads();

    int row = blockIdx.x*256 + t;
    float in[64];
    #pragma unroll
    for (int cc=0;cc<32;cc++){
        in[cc]    = fmaf(s2[cc], g_Sagg[row*32+cc], 128.0f*t2[cc]);
        in[32+cc] = g_x[row*32+cc];
    }
    float z[32];
    #pragma unroll
    for (int cc=0;cc<32;cc++) z[cc] = bsh[cc];
    #pragma unroll
    for (int kk=0;kk<64;kk++){
        float xv = in[kk];
        #pragma unroll
        for (int cc=0;cc<32;cc++) z[cc] = fmaf(xv, W[kk*32+cc], z[cc]);
    }
    int lane = t & 31;
    #pragma unroll
    for (int cc=0;cc<32;cc++){
        float h = lrelu(z[cc]);
        g_h1[row*32+cc] = h;
        float v1 = h, v2 = h*h;
        #pragma unroll
        for (int off=16; off>0; off>>=1){
            v1 += __shfl_xor_sync(0xFFFFFFFFu, v1, off);
            v2 += __shfl_xor_sync(0xFFFFFFFFu, v2, off);
        }
        if (lane == 0){ atomicAdd(&ssum[cc], v1); atomicAdd(&sssum[cc], v2); }
    }
    __syncthreads();
    if (t < 32){
        atomicAdd(&g_sh0[t], (double)ssum[t]);
        atomicAdd(&g_ssh0[t], (double)sssum[t]);
    }
}

// ---------------- node layer 1 -----------------------------------------
__global__ void __launch_bounds__(256) k_node1(const float* __restrict__ Wn_i,
                                               const float* __restrict__ bnn_i,
                                               const float* __restrict__ gn0,
                                               const float* __restrict__ bn0v){
    __shared__ float W[1024];
    __shared__ float s0[32], t0[32], bsh[32], ssum[32], sssum[32];
    int t = threadIdx.x;
    if (t < 32){
        double m = g_sh0[t]/NT_D;
        double v = g_ssh0[t]/NT_D - m*m;
        float s = gn0[t] * rsqrtf((float)v + BNEPS);
        s0[t] = s; t0[t] = bn0v[t] - (float)m*s;
        bsh[t] = bnn_i[t]; ssum[t] = 0.0f; sssum[t] = 0.0f;
    }
    for (int idx=t; idx<1024; idx+=256) W[idx] = Wn_i[idx];
    __syncthreads();

    int row = blockIdx.x*256 + t;
    float hn[32];
    #pragma unroll
    for (int kk=0;kk<32;kk++) hn[kk] = fmaf(s0[kk], g_h1[row*32+kk], t0[kk]);
    float z[32];
    #pragma unroll
    for (int cc=0;cc<32;cc++) z[cc] = bsh[cc];
    #pragma unroll
    for (int kk=0;kk<32;kk++){
        float xv = hn[kk];
        #pragma unroll
        for (int cc=0;cc<32;cc++) z[cc] = fmaf(xv, W[kk*32+cc], z[cc]);
    }
    int lane = t & 31;
    #pragma unroll
    for (int cc=0;cc<32;cc++){
        float h = lrelu(z[cc]);
        g_h2[row*32+cc] = h;
        float v1 = h, v2 = h*h;
        #pragma unroll
        for (int off=16; off>0; off>>=1){
            v1 += __shfl_xor_sync(0xFFFFFFFFu, v1, off);
            v2 += __shfl_xor_sync(0xFFFFFFFFu, v2, off);
        }
        if (lane == 0){ atomicAdd(&ssum[cc], v1); atomicAdd(&sssum[cc], v2); }
    }
    __syncthreads();
    if (t < 32){
        atomicAdd(&g_sh1[t], (double)ssum[t]);
        atomicAdd(&g_ssh1[t], (double)sssum[t]);
    }
}

// ---------------- node final: update linear + tanh ---------------------
__global__ void __launch_bounds__(256) k_node2(const float* __restrict__ Wu_i,
                                               const float* __restrict__ bu_i,
                                               const float* __restrict__ gn1,
                                               const float* __restrict__ bn1v,
                                               float* __restrict__ out,
                                               int is_last){
    __shared__ float W[1024];
    __shared__ float s0[32], t0[32], bsh[32];
    int t = threadIdx.x;
    if (t < 32){
        double m = g_sh1[t]/NT_D;
        double v = g_ssh1[t]/NT_D - m*m;
        float s = gn1[t] * rsqrtf((float)v + BNEPS);
        s0[t] = s; t0[t] = bn1v[t] - (float)m*s;
        bsh[t] = bu_i[t];
    }
    for (int idx=t; idx<1024; idx+=256) W[idx] = Wu_i[idx];
    __syncthreads();

    int row = blockIdx.x*256 + t;
    float hn[32];
    #pragma unroll
    for (int kk=0;kk<32;kk++) hn[kk] = fmaf(s0[kk], g_h2[row*32+kk], t0[kk]);
    float z[32];
    #pragma unroll
    for (int cc=0;cc<32;cc++) z[cc] = bsh[cc];
    #pragma unroll
    for (int kk=0;kk<32;kk++){
        float xv = hn[kk];
        #pragma unroll
        for (int cc=0;cc<32;cc++) z[cc] = fmaf(xv, W[kk*32+cc], z[cc]);
    }
    #pragma unroll
    for (int cc=0;cc<32;cc++){
        float o = tanhf(z[cc]);
        g_x[row*32+cc] = o;
        if (is_last) out[row*32+cc] = o;
    }
}

// ----------------------------------------------------------------------
extern "C" void kernel_launch(void* const* d_in, const int* in_sizes, int n_in,
                              void* d_out, int out_size){
    const float* x    = (const float*)d_in[0];
    const float* Wah  = (const float*)d_in[1];
    const float* bah  = (const float*)d_in[2];
    const float* Wa   = (const float*)d_in[3];
    const float* ba   = (const float*)d_in[4];
    const float* geh  = (const float*)d_in[5];
    const float* beh  = (const float*)d_in[6];
    const float* ge   = (const float*)d_in[7];
    const float* be   = (const float*)d_in[8];
    const float* Wn0  = (const float*)d_in[9];
    const float* bn0  = (const float*)d_in[10];
    const float* Wn   = (const float*)d_in[11];
    const float* bnn  = (const float*)d_in[12];
    const float* gn   = (const float*)d_in[13];
    const float* bnv  = (const float*)d_in[14];
    const float* Wu   = (const float*)d_in[15];
    const float* bu   = (const float*)d_in[16];
    float* out = (float*)d_out;

    const size_t SMEM_STATS = (8192 + 4224 + 4096 + 256)*sizeof(float);
    cudaFuncSetAttribute(k_edge_stats, cudaFuncAttributeMaxDynamicSharedMemorySize, (int)SMEM_STATS);
    cudaFuncSetAttribute(k_edge_main,  cudaFuncAttributeMaxDynamicSharedMemorySize, SMEM_MAIN_BYTES);

    k_pad<<<NT*HH/256, 256>>>(x);

    for (int i=0; i<4; i++){
        k_zero<<<1,128>>>();
        k_pre<<<128,256>>>(Wah + i*66*64, bah + i*64);
        k_edge_stats<<<dim3(16,64),256,SMEM_STATS>>>(Wah + i*66*64);
        k_fold1<<<1,256>>>(Wa + i*64*32, ba + i*32, geh + i*64, beh + i*64);
        k_edge_main<<<dim3(8,64),256,SMEM_MAIN_BYTES>>>(Wah + i*66*64);
        k_node0<<<32,256>>>(Wn0 + i*64*32, bn0 + i*32, ge + i*32, be + i*32);
        k_node1<<<32,256>>>(Wn + i*32*32, bnn + i*32, gn + (i*2+0)*32, bnv + (i*2+0)*32);
        k_node2<<<32,256>>>(Wu + i*32*32, bu + i*32, gn + (i*2+1)*32, bnv + (i*2+1)*32,
                            out, (i==3) ? 1 : 0);
    }
}

// round 7
// speedup vs baseline: 2.4114x; 1.3194x over previous
#include <cuda_runtime.h>
#include <cuda_bf16.h>
#include <math.h>
#include <stdint.h>

#define BB 64
#define NNODES 128
#define HH 32
#define HEc 64
#define OEc 32
#define NT (BB*NNODES)
#define ALPHA 0.1f
#define BNEPS 1e-5f

static const double NE_D = 1048576.0;  // B*N*N edges
static const double NT_D = 8192.0;     // B*N nodes

// ----------------- device scratch (no allocs allowed) -----------------
__device__ __align__(16) float g_x[NT*HH];
__device__ __align__(16) float g_Q1[NT*HEc];
__device__ __align__(16) float g_P2[NT*HEc];
__device__ __align__(16) float g_Sagg[NT*OEc];
__device__ __align__(16) float g_h1[NT*HH];
__device__ __align__(16) float g_h2[NT*HH];
__device__ double g_su[HEc],  g_ssu[HEc];
__device__ double g_sv[OEc],  g_ssv[OEc];
__device__ double g_sh0[HH],  g_ssh0[HH];
__device__ double g_sh1[HH],  g_ssh1[HH];

__device__ __forceinline__ float lrelu(float z){ return fmaxf(z, ALPHA*z); }

// ---------------- warp-MMA helpers (base ISA: sm_80+) -------------------
__device__ __forceinline__ uint32_t s2u(const void* p){
    return (uint32_t)__cvta_generic_to_shared(p);
}
__device__ __forceinline__ void ldmx4(uint32_t* r, uint32_t a){
    asm volatile("ldmatrix.sync.aligned.m8n8.x4.shared.b16 {%0,%1,%2,%3}, [%4];"
        : "=r"(r[0]),"=r"(r[1]),"=r"(r[2]),"=r"(r[3]) : "r"(a));
}
__device__ __forceinline__ void ldmx2(uint32_t* r, uint32_t a){
    asm volatile("ldmatrix.sync.aligned.m8n8.x2.shared.b16 {%0,%1}, [%2];"
        : "=r"(r[0]),"=r"(r[1]) : "r"(a));
}
__device__ __forceinline__ void mma16816(float* c, const uint32_t* a, const uint32_t* b){
    asm volatile("mma.sync.aligned.m16n8k16.row.col.f32.bf16.bf16.f32 "
        "{%0,%1,%2,%3}, {%4,%5,%6,%7}, {%8,%9}, {%0,%1,%2,%3};"
        : "+f"(c[0]),"+f"(c[1]),"+f"(c[2]),"+f"(c[3])
        : "r"(a[0]),"r"(a[1]),"r"(a[2]),"r"(a[3]), "r"(b[0]),"r"(b[1]));
}

// ----------------------------------------------------------------------
__global__ void k_pad(const float* __restrict__ xin){
    int i = blockIdx.x*256 + threadIdx.x;
    if (i < NT*HH){
        int node = i >> 5, k = i & 31;
        g_x[i] = (k < 3) ? xin[node*3 + k] : 0.0f;
    }
}

// Q1 = x@Wah[0:32] + bah ; P2 = x@Wah[32:64]  (+ block 0 zeroes accumulators)
__global__ void __launch_bounds__(256) k_pre(const float* __restrict__ Wah_i,
                                             const float* __restrict__ bah_i){
    __shared__ float xs[64*33];
    __shared__ float W1s[32*64];
    __shared__ float W2s[32*64];
    __shared__ float bs[64];
    int t = threadIdx.x;
    int n0 = blockIdx.x*64;
    if (blockIdx.x == 0){
        if (t < 64){ g_su[t]=0.0; g_ssu[t]=0.0; }
        if (t < 32){ g_sv[t]=0.0; g_ssv[t]=0.0;
                     g_sh0[t]=0.0; g_ssh0[t]=0.0;
                     g_sh1[t]=0.0; g_ssh1[t]=0.0; }
    }
    for (int idx=t; idx<64*32; idx+=256){
        int n = idx>>5, k = idx&31;
        xs[n*33+k] = g_x[(n0+n)*32 + k];
    }
    for (int idx=t; idx<32*64; idx+=256){
        int k = idx>>6, c = idx&63;
        W1s[idx] = Wah_i[k*64 + c];
        W2s[idx] = Wah_i[(32+k)*64 + c];
    }
    if (t < 64) bs[t] = bah_i[t];
    __syncthreads();
    int c = t & 63, ng = t >> 6;
    for (int n=ng; n<64; n+=4){
        float q = bs[c], p = 0.0f;
        #pragma unroll
        for (int k=0;k<32;k++){
            float xv = xs[n*33+k];
            q = fmaf(xv, W1s[k*64+c], q);
            p = fmaf(xv, W2s[k*64+c], p);
        }
        g_Q1[(n0+n)*64 + c] = q;
        g_P2[(n0+n)*64 + c] = p;
    }
}

// ---------------- edge pass 1: stats of u = lrelu(z1) ------------------
__global__ void __launch_bounds__(256) k_edge_stats(const float* __restrict__ Wah_i){
    extern __shared__ float sm[];
    float*  xr  = sm;                       // 4224
    float2* de  = (float2*)(xr + 4224);     // 2048 float2
    float*  red = (float*)(de + 2048);      // 256

    int t  = threadIdx.x;
    int b  = blockIdx.y;
    int a0 = blockIdx.x*16;

    for (int idx=t; idx<4096; idx+=256){
        int r = idx>>5, kk = idx&31;
        xr[r*33+kk] = g_x[b*4096 + idx];
    }
    __syncthreads();

    #pragma unroll
    for (int j=0;j<8;j++){
        int e  = t + 256*j;
        int as = e >> 7, p = e & 127;
        const float* xra = xr + (a0+as)*33;
        const float* xrp = xr + p*33;
        float s = 0.0f;
        #pragma unroll
        for (int kk=0;kk<31;kk++){
            float df = xrp[kk] - xra[kk] + 1e-12f;
            s = fmaf(df, df, s);
        }
        de[e] = make_float2(sqrtf(s), 1.0f - (xrp[31]-xra[31]));
    }
    __syncthreads();

    int k = t & 63, g = t >> 6;
    const float* P2b = g_P2 + (size_t)b*8192;
    float wdk = __ldg(Wah_i + 64*64 + k);
    float wik = __ldg(Wah_i + 65*64 + k);
    float q[16];
    #pragma unroll
    for (int as=0; as<16; as++) q[as] = __ldg(&g_Q1[(size_t)(b*128+a0+as)*64 + k]);

    float su = 0.0f, ssu = 0.0f;
    float pvn = __ldg(&P2b[g*64 + k]);
    #pragma unroll 2
    for (int m=0; m<32; m++){
        float pv = pvn;
        if (m < 31) pvn = __ldg(&P2b[(g + 4*(m+1))*64 + k]);
        int p = g + 4*m;
        #pragma unroll
        for (int as=0; as<16; as++){
            float2 e2 = de[as*128+p];
            float z = fmaf(e2.x, wdk, q[as] + pv);
            z = fmaf(e2.y, wik, z);
            float u = fmaxf(z, ALPHA*z);
            su += u; ssu = fmaf(u,u,ssu);
        }
    }
    red[g*64+k] = su;
    __syncthreads();
    if (g == 0)
        atomicAdd(&g_su[k], (double)(red[k]+red[64+k]+red[128+k]+red[192+k]));
    __syncthreads();
    red[g*64+k] = ssu;
    __syncthreads();
    if (g == 0)
        atomicAdd(&g_ssu[k], (double)(red[k]+red[64+k]+red[128+k]+red[192+k]));
}

// ---------------- edge pass 2: HMMA main kernel (fold inlined) ----------
// byte offsets from 1024-aligned base
#define OFF_DE    0        // 16384
#define OFF_Q1A   16384    // 4096
#define OFF_UHI   20480    // 18432 (rows 144B)  [xr transient alias]
#define OFF_ULO   38912    // 18432
#define OFF_WTHI  57344    // 4608 (32 rows x 144B)
#define OFF_WTLO  61952    // 4608
#define OFF_RED   66560    // 2048 (two 8x32 float)
#define OFF_BAF   68608    // 128
#define OFF_S1    68736    // 256
#define OFF_T1    68992    // 256
#define SMEM_MAIN_BYTES (1024 + 69248)
#define ROWB 144

__global__ void __launch_bounds__(256, 2) k_edge_main(
        const float* __restrict__ Wah_i,
        const float* __restrict__ Wa_i,  const float* __restrict__ ba_i,
        const float* __restrict__ geh_i, const float* __restrict__ beh_i){
    extern __shared__ char smraw[];
    char* A0 = (char*)(((uintptr_t)smraw + 1023) & ~(uintptr_t)1023);

    float2* de   = (float2*)(A0 + OFF_DE);
    float*  Q1a  = (float*)(A0 + OFF_Q1A);
    char*   uhi  = A0 + OFF_UHI;
    char*   ulo  = A0 + OFF_ULO;
    char*   wthi = A0 + OFF_WTHI;
    char*   wtlo = A0 + OFF_WTLO;
    float*  xr   = (float*)uhi;            // transient (16896B <= 36864B)
    float*  red  = (float*)(A0 + OFF_RED); // [8][32]
    float*  sqr  = red + 256;              // [8][32]
    float*  bafs = (float*)(A0 + OFF_BAF);
    float*  s1   = (float*)(A0 + OFF_S1);
    float*  t1   = (float*)(A0 + OFF_T1);

    int t    = threadIdx.x;
    int w    = t >> 5, lane = t & 31;
    int b    = blockIdx.y;
    int a0   = blockIdx.x*16;

    // --- prologue stage 1: xr, Q1a, BN1 scale/shift ---
    for (int idx=t; idx<4096; idx+=256){
        int r = idx>>5, kk = idx&31;
        xr[r*33+kk] = g_x[b*4096 + idx];
    }
    for (int idx=t; idx<1024; idx+=256)
        Q1a[idx] = g_Q1[(size_t)(b*128+a0)*64 + idx];
    if (t < 64){
        double m = g_su[t]/NE_D;
        double v = g_ssu[t]/NE_D - m*m;
        float s = geh_i[t] * rsqrtf((float)v + BNEPS);
        s1[t] = s; t1[t] = beh_i[t] - (float)m*s;
    }
    __syncthreads();

    // --- prologue stage 2: distances, folded W split, bias fold ---
    #pragma unroll
    for (int j=0;j<8;j++){
        int e  = t + 256*j;
        int as = e >> 7, p = e & 127;
        const float* xra = xr + (a0+as)*33;
        const float* xrp = xr + p*33;
        float s = 0.0f;
        #pragma unroll
        for (int kk=0;kk<31;kk++){
            float df = xrp[kk] - xra[kk] + 1e-12f;
            s = fmaf(df, df, s);
        }
        de[e] = make_float2(sqrtf(s), 1.0f - (xrp[31]-xra[31]));
    }
    for (int idx=t; idx<2048; idx+=256){
        int c = idx>>6, k = idx&63;
        float wv = s1[k]*Wa_i[k*32+c];
        __nv_bfloat16 hi = __float2bfloat16(wv);
        *(__nv_bfloat16*)(wthi + c*ROWB + k*2) = hi;
        *(__nv_bfloat16*)(wtlo + c*ROWB + k*2) =
            __float2bfloat16(wv - __bfloat162float(hi));
    }
    if (t < 32){
        float acc = ba_i[t];
        #pragma unroll
        for (int k=0;k<64;k++) acc = fmaf(t1[k], Wa_i[k*32+t], acc);
        bafs[t] = acc;
    }
    __syncthreads();   // xr dead; uhi/ulo free; wthi/wtlo/bafs ready

    // --- persistent B fragments (W^T), per warp ---
    uint32_t bh[4][4][2], bl[4][4][2];
    {
        int li = lane & 15;
        uint32_t rsel = (uint32_t)((li & 7)*ROWB);
        uint32_t ksel = (uint32_t)((li >> 3)*16);
        #pragma unroll
        for (int kt=0; kt<4; kt++){
            #pragma unroll
            for (int nt=0; nt<4; nt++){
                uint32_t off = (uint32_t)(nt*8*ROWB) + rsel + (uint32_t)(kt*32) + ksel;
                ldmx2(bh[kt][nt], s2u(wthi) + off);
                ldmx2(bl[kt][nt], s2u(wtlo) + off);
            }
        }
    }
    int tc = lane & 3;
    float bias0[4], bias1[4];
    #pragma unroll
    for (int nt=0; nt<4; nt++){
        bias0[nt] = bafs[8*nt + 2*tc];
        bias1[nt] = bafs[8*nt + 2*tc + 1];
    }

    // phase-A per-thread constants
    int kp = lane;                         // k-pair 0..31
    float wd0 = __ldg(Wah_i + 64*64 + 2*kp), wd1 = __ldg(Wah_i + 64*64 + 2*kp + 1);
    float wi0 = __ldg(Wah_i + 65*64 + 2*kp), wi1 = __ldg(Wah_i + 65*64 + 2*kp + 1);
    const float2* P2b = (const float2*)(g_P2 + (size_t)b*8192);

    uint32_t aoff = (uint32_t)((w*16 + (lane & 15))*ROWB) + ((lane & 16) ? 16u : 0u);
    uint32_t uhiB = s2u(uhi), uloB = s2u(ulo);

    float vtot = 0.0f, ssvtot = 0.0f;      // t<32 only

    for (int as=0; as<16; as++){
        // ---- phase A: u -> bf16 hi/lo tiles ----
        {
            float2 q = *(const float2*)(Q1a + as*64 + 2*kp);
            #pragma unroll
            for (int j=0;j<16;j++){
                int p = w + 8*j;
                float2 pv = __ldg(&P2b[p*32 + kp]);
                float2 dd = de[as*128 + p];
                float z0 = fmaf(dd.x, wd0, q.x + pv.x); z0 = fmaf(dd.y, wi0, z0);
                float z1 = fmaf(dd.x, wd1, q.y + pv.y); z1 = fmaf(dd.y, wi1, z1);
                float u0 = fmaxf(z0, ALPHA*z0);
                float u1 = fmaxf(z1, ALPHA*z1);
                __nv_bfloat162 h2 = __floats2bfloat162_rn(u0, u1);
                float2 hf = __bfloat1622float2(h2);
                __nv_bfloat162 l2 = __floats2bfloat162_rn(u0 - hf.x, u1 - hf.y);
                *(__nv_bfloat162*)(uhi + p*ROWB + kp*4) = h2;
                *(__nv_bfloat162*)(ulo + p*ROWB + kp*4) = l2;
            }
        }
        __syncthreads();

        // ---- phase B: 3-pass bf16 HMMA, accumulate fp32 ----
        float C[4][4];
        #pragma unroll
        for (int nt=0;nt<4;nt++){
            C[nt][0]=0.f; C[nt][1]=0.f; C[nt][2]=0.f; C[nt][3]=0.f;
        }
        #pragma unroll
        for (int kt=0; kt<4; kt++){
            uint32_t ah[4], al[4];
            ldmx4(ah, uhiB + aoff + kt*32);
            ldmx4(al, uloB + aoff + kt*32);
            #pragma unroll
            for (int nt=0; nt<4; nt++){
                mma16816(C[nt], ah, bh[kt][nt]);
                mma16816(C[nt], ah, bl[kt][nt]);
                mma16816(C[nt], al, bh[kt][nt]);
            }
        }

        // ---- epilogue: bias + lrelu, row-sum + sq-sum per channel ----
        #pragma unroll
        for (int nt=0; nt<4; nt++){
            float y00 = C[nt][0] + bias0[nt];
            float y01 = C[nt][1] + bias1[nt];
            float y10 = C[nt][2] + bias0[nt];
            float y11 = C[nt][3] + bias1[nt];
            float v00 = fmaxf(y00, ALPHA*y00);
            float v01 = fmaxf(y01, ALPHA*y01);
            float v10 = fmaxf(y10, ALPHA*y10);
            float v11 = fmaxf(y11, ALPHA*y11);
            float cs0 = v00 + v10, cs1 = v01 + v11;
            float sq0 = fmaf(v00,v00, v10*v10);
            float sq1 = fmaf(v01,v01, v11*v11);
            #pragma unroll
            for (int off=4; off<32; off<<=1){
                cs0 += __shfl_xor_sync(0xFFFFFFFFu, cs0, off);
                cs1 += __shfl_xor_sync(0xFFFFFFFFu, cs1, off);
                sq0 += __shfl_xor_sync(0xFFFFFFFFu, sq0, off);
                sq1 += __shfl_xor_sync(0xFFFFFFFFu, sq1, off);
            }
            if (lane < 4){
                red[w*32 + 8*nt + 2*tc]     = cs0;
                red[w*32 + 8*nt + 2*tc + 1] = cs1;
                sqr[w*32 + 8*nt + 2*tc]     = sq0;
                sqr[w*32 + 8*nt + 2*tc + 1] = sq1;
            }
        }
        __syncthreads();
        if (t < 32){
            float S = 0.0f, SS = 0.0f;
            #pragma unroll
            for (int j=0;j<8;j++){ S += red[j*32 + t]; SS += sqr[j*32 + t]; }
            g_Sagg[(size_t)(b*128 + a0 + as)*32 + t] = S;
            vtot += S; ssvtot += SS;
        }
    }

    if (t < 32){
        atomicAdd(&g_sv[t],  (double)vtot);
        atomicAdd(&g_ssv[t], (double)ssvtot);
    }
}

// ---------------- node layer 0 (staged, coalesced) ---------------------
__global__ void __launch_bounds__(128) k_node0(const float* __restrict__ Wn0_i,
                                               const float* __restrict__ bn0_i,
                                               const float* __restrict__ ge_i,
                                               const float* __restrict__ be_i){
    __shared__ float W[2048];
    __shared__ float sA[4096];
    __shared__ float sX[4096];
    __shared__ float s2[32], t2[32], bsh[32], ssum[32], sssum[32];
    int t = threadIdx.x;
    int row0 = blockIdx.x*128;
    if (t < 32){
        double m = g_sv[t]/NE_D;
        double v = g_ssv[t]/NE_D - m*m;
        float s = ge_i[t] * rsqrtf((float)v + BNEPS);
        s2[t] = s; t2[t] = be_i[t] - (float)m*s;
        bsh[t] = bn0_i[t]; ssum[t] = 0.0f; sssum[t] = 0.0f;
    }
    for (int idx=t; idx<512; idx+=128)
        ((float4*)W)[idx] = ((const float4*)Wn0_i)[idx];
    for (int idx=t; idx<1024; idx+=128){
        ((float4*)sA)[idx] = ((const float4*)(g_Sagg + (size_t)row0*32))[idx];
        ((float4*)sX)[idx] = ((const float4*)(g_x    + (size_t)row0*32))[idx];
    }
    __syncthreads();

    float in[64];
    #pragma unroll
    for (int cc=0;cc<32;cc++){
        in[cc]    = fmaf(s2[cc], sA[t*32+cc], 128.0f*t2[cc]);
        in[32+cc] = sX[t*32+cc];
    }
    float z[32];
    #pragma unroll
    for (int cc=0;cc<32;cc++) z[cc] = bsh[cc];
    const float4* W4 = (const float4*)W;
    #pragma unroll
    for (int kk=0;kk<64;kk++){
        float xv = in[kk];
        #pragma unroll
        for (int j=0;j<8;j++){
            float4 wv = W4[kk*8+j];
            z[4*j+0] = fmaf(xv, wv.x, z[4*j+0]);
            z[4*j+1] = fmaf(xv, wv.y, z[4*j+1]);
            z[4*j+2] = fmaf(xv, wv.z, z[4*j+2]);
            z[4*j+3] = fmaf(xv, wv.w, z[4*j+3]);
        }
    }
    int lane = t & 31;
    #pragma unroll
    for (int cc=0;cc<32;cc++){
        float h = lrelu(z[cc]);
        sA[t*32+cc] = h;
        float v1 = h, v2 = h*h;
        #pragma unroll
        for (int off=16; off>0; off>>=1){
            v1 += __shfl_xor_sync(0xFFFFFFFFu, v1, off);
            v2 += __shfl_xor_sync(0xFFFFFFFFu, v2, off);
        }
        if (lane == 0){ atomicAdd(&ssum[cc], v1); atomicAdd(&sssum[cc], v2); }
    }
    __syncthreads();
    for (int idx=t; idx<1024; idx+=128)
        ((float4*)(g_h1 + (size_t)row0*32))[idx] = ((float4*)sA)[idx];
    if (t < 32){
        atomicAdd(&g_sh0[t], (double)ssum[t]);
        atomicAdd(&g_ssh0[t], (double)sssum[t]);
    }
}

// ---------------- node layer 1 -----------------------------------------
__global__ void __launch_bounds__(128) k_node1(const float* __restrict__ Wn_i,
                                               const float* __restrict__ bnn_i,
                                               const float* __restrict__ gn0,
                                               const float* __restrict__ bn0v){
    __shared__ float W[1024];
    __shared__ float sH[4096];
    __shared__ float s0[32], t0[32], bsh[32], ssum[32], sssum[32];
    int t = threadIdx.x;
    int row0 = blockIdx.x*128;
    if (t < 32){
        double m = g_sh0[t]/NT_D;
        double v = g_ssh0[t]/NT_D - m*m;
        float s = gn0[t] * rsqrtf((float)v + BNEPS);
        s0[t] = s; t0[t] = bn0v[t] - (float)m*s;
        bsh[t] = bnn_i[t]; ssum[t] = 0.0f; sssum[t] = 0.0f;
    }
    for (int idx=t; idx<256; idx+=128)
        ((float4*)W)[idx] = ((const float4*)Wn_i)[idx];
    for (int idx=t; idx<1024; idx+=128)
        ((float4*)sH)[idx] = ((const float4*)(g_h1 + (size_t)row0*32))[idx];
    __syncthreads();

    float hn[32];
    #pragma unroll
    for (int kk=0;kk<32;kk++) hn[kk] = fmaf(s0[kk], sH[t*32+kk], t0[kk]);
    float z[32];
    #pragma unroll
    for (int cc=0;cc<32;cc++) z[cc] = bsh[cc];
    const float4* W4 = (const float4*)W;
    #pragma unroll
    for (int kk=0;kk<32;kk++){
        float xv = hn[kk];
        #pragma unroll
        for (int j=0;j<8;j++){
            float4 wv = W4[kk*8+j];
            z[4*j+0] = fmaf(xv, wv.x, z[4*j+0]);
            z[4*j+1] = fmaf(xv, wv.y, z[4*j+1]);
            z[4*j+2] = fmaf(xv, wv.z, z[4*j+2]);
            z[4*j+3] = fmaf(xv, wv.w, z[4*j+3]);
        }
    }
    int lane = t & 31;
    #pragma unroll
    for (int cc=0;cc<32;cc++){
        float h = lrelu(z[cc]);
        sH[t*32+cc] = h;
        float v1 = h, v2 = h*h;
        #pragma unroll
        for (int off=16; off>0; off>>=1){
            v1 += __shfl_xor_sync(0xFFFFFFFFu, v1, off);
            v2 += __shfl_xor_sync(0xFFFFFFFFu, v2, off);
        }
        if (lane == 0){ atomicAdd(&ssum[cc], v1); atomicAdd(&sssum[cc], v2); }
    }
    __syncthreads();
    for (int idx=t; idx<1024; idx+=128)
        ((float4*)(g_h2 + (size_t)row0*32))[idx] = ((float4*)sH)[idx];
    if (t < 32){
        atomicAdd(&g_sh1[t], (double)ssum[t]);
        atomicAdd(&g_ssh1[t], (double)sssum[t]);
    }
}

// ---------------- node final: update linear + tanh ---------------------
__global__ void __launch_bounds__(128) k_node2(const float* __restrict__ Wu_i,
                                               const float* __restrict__ bu_i,
                                               const float* __restrict__ gn1,
                                               const float* __restrict__ bn1v,
                                               float* __restrict__ out,
                                               int is_last){
    __shared__ float W[1024];
    __shared__ float sH[4096];
    __shared__ float s0[32], t0[32], bsh[32];
    int t = threadIdx.x;
    int row0 = blockIdx.x*128;
    if (t < 32){
        double m = g_sh1[t]/NT_D;
        double v = g_ssh1[t]/NT_D - m*m;
        float s = gn1[t] * rsqrtf((float)v + BNEPS);
        s0[t] = s; t0[t] = bn1v[t] - (float)m*s;
        bsh[t] = bu_i[t];
    }
    for (int idx=t; idx<256; idx+=128)
        ((float4*)W)[idx] = ((const float4*)Wu_i)[idx];
    for (int idx=t; idx<1024; idx+=128)
        ((float4*)sH)[idx] = ((const float4*)(g_h2 + (size_t)row0*32))[idx];
    __syncthreads();

    float hn[32];
    #pragma unroll
    for (int kk=0;kk<32;kk++) hn[kk] = fmaf(s0[kk], sH[t*32+kk], t0[kk]);
    float z[32];
    #pragma unroll
    for (int cc=0;cc<32;cc++) z[cc] = bsh[cc];
    const float4* W4 = (const float4*)W;
    #pragma unroll
    for (int kk=0;kk<32;kk++){
        float xv = hn[kk];
        #pragma unroll
        for (int j=0;j<8;j++){
            float4 wv = W4[kk*8+j];
            z[4*j+0] = fmaf(xv, wv.x, z[4*j+0]);
            z[4*j+1] = fmaf(xv, wv.y, z[4*j+1]);
            z[4*j+2] = fmaf(xv, wv.z, z[4*j+2]);
            z[4*j+3] = fmaf(xv, wv.w, z[4*j+3]);
        }
    }
    #pragma unroll
    for (int cc=0;cc<32;cc++) sH[t*32+cc] = tanhf(z[cc]);
    __syncthreads();
    for (int idx=t; idx<1024; idx+=128){
        float4 o4 = ((float4*)sH)[idx];
        ((float4*)(g_x + (size_t)row0*32))[idx] = o4;
        if (is_last) ((float4*)(out + (size_t)row0*32))[idx] = o4;
    }
}

// ----------------------------------------------------------------------
extern "C" void kernel_launch(void* const* d_in, const int* in_sizes, int n_in,
                              void* d_out, int out_size){
    const float* x    = (const float*)d_in[0];
    const float* Wah  = (const float*)d_in[1];
    const float* bah  = (const float*)d_in[2];
    const float* Wa   = (const float*)d_in[3];
    const float* ba   = (const float*)d_in[4];
    const float* geh  = (const float*)d_in[5];
    const float* beh  = (const float*)d_in[6];
    const float* ge   = (const float*)d_in[7];
    const float* be   = (const float*)d_in[8];
    const float* Wn0  = (const float*)d_in[9];
    const float* bn0  = (const float*)d_in[10];
    const float* Wn   = (const float*)d_in[11];
    const float* bnn  = (const float*)d_in[12];
    const float* gn   = (const float*)d_in[13];
    const float* bnv  = (const float*)d_in[14];
    const float* Wu   = (const float*)d_in[15];
    const float* bu   = (const float*)d_in[16];
    float* out = (float*)d_out;

    const size_t SMEM_STATS = (4224 + 4096 + 256)*sizeof(float);   // 34304
    cudaFuncSetAttribute(k_edge_stats, cudaFuncAttributeMaxDynamicSharedMemorySize, (int)SMEM_STATS);
    cudaFuncSetAttribute(k_edge_main,  cudaFuncAttributeMaxDynamicSharedMemorySize, SMEM_MAIN_BYTES);

    k_pad<<<NT*HH/256, 256>>>(x);

    for (int i=0; i<4; i++){
        k_pre<<<128,256>>>(Wah + i*66*64, bah + i*64);
        k_edge_stats<<<dim3(8,64),256,SMEM_STATS>>>(Wah + i*66*64);
        k_edge_main<<<dim3(8,64),256,SMEM_MAIN_BYTES>>>(Wah + i*66*64,
                                                        Wa + i*64*32, ba + i*32,
                                                        geh + i*64, beh + i*64);
        k_node0<<<64,128>>>(Wn0 + i*64*32, bn0 + i*32, ge + i*32, be + i*32);
        k_node1<<<64,128>>>(Wn + i*32*32, bnn + i*32, gn + (i*2+0)*32, bnv + (i*2+0)*32);
        k_node2<<<64,128>>>(Wu + i*32*32, bu + i*32, gn + (i*2+1)*32, bnv + (i*2+1)*32,
                            out, (i==3) ? 1 : 0);
    }
}